// round 3
// baseline (speedup 1.0000x reference)
#include <cuda_runtime.h>
#include <cuda_bf16.h>

// SMPL forward kinematics, algebraically simplified:
//   out[b,j,:] = sum over ancestors a of j (a with a parent) of
//                R[b, parent(a)] @ offp[a],   offp = (off.y, off.z, off.x)
// (G is a permutation matrix; the G / G^T einsums cancel through the chain.)
//
// Pure HBM-streaming kernel: coalesced scalar LDG -> padded smem (lane-stride-1
// STS, conflict-free), per-thread prefix walk over the 24-joint tree from smem
// (lane stride 217, coprime w/ 32 banks), conflict-free restage, coalesced STG.
//
// Occupancy tuned for DRAM latency hiding: 55.5 KB smem/block -> 4 blocks/SM,
// 16 warps/SM, staging unrolled x8 => ~16 KB reads in flight per SM.

#define BPB      64    // bodies per block
#define THREADS  128
#define SPITCH   217   // 216 floats/body + 1 pad (coprime with 32 banks)
#define OPITCH   73    // 72 floats/body + 1 pad (coprime with 32 banks)

__global__ void __launch_bounds__(THREADS, 4)
smpl_skel_kernel(const float* __restrict__ R,
                 const float* __restrict__ off,
                 float* __restrict__ out,
                 int B)
{
    extern __shared__ float s[];           // BPB * SPITCH floats; reused for output
    __shared__ float soff[72];

    const int tid = threadIdx.x;
    if (tid < 72) soff[tid] = off[tid];

    const int base = blockIdx.x * BPB;
    const int nb   = min(BPB, B - base);

    // ---- Stage input: coalesced scalar LDG, conflict-free STS ----
    // Consecutive lanes take consecutive i -> contiguous 128B global segments,
    // smem lane stride 1 within a body -> no bank conflicts.
    const float* ing = R + (size_t)base * 216;
    const int total = nb * 216;            // 13824 for a full block
    #pragma unroll 8
    for (int i = tid; i < total; i += THREADS) {
        int body = i / 216;
        int e    = i - body * 216;
        s[body * SPITCH + e] = ing[i];
    }
    __syncthreads();

    // ---- Per-thread forward kinematics (threads 0..nb-1) ----
    float px[24], py[24], pz[24];
    if (tid < nb) {
        const float* m = s + tid * SPITCH;   // 24 row-major 3x3 matrices
        px[0] = py[0] = pz[0] = 0.0f;
        const int par[24] = {-1, 0, 1, 2, 3, 0, 5, 6, 7, 0, 9, 10, 11, 12,
                             11, 14, 15, 16, 17, 11, 19, 20, 21, 22};
        #pragma unroll
        for (int j = 1; j < 24; ++j) {
            const int p = par[j];
            const float ox = soff[j * 3 + 1];   // offp = (off.y, off.z, off.x)
            const float oy = soff[j * 3 + 2];
            const float oz = soff[j * 3 + 0];
            const float* Rp = m + p * 9;
            px[j] = fmaf(Rp[0], ox, fmaf(Rp[1], oy, fmaf(Rp[2], oz, px[p])));
            py[j] = fmaf(Rp[3], ox, fmaf(Rp[4], oy, fmaf(Rp[5], oz, py[p])));
            pz[j] = fmaf(Rp[6], ox, fmaf(Rp[7], oy, fmaf(Rp[8], oz, pz[p])));
        }
    }
    __syncthreads();   // input staging fully consumed -> safe to reuse smem

    // ---- Restage output (lane stride OPITCH=73, conflict-free) ----
    if (tid < nb) {
        float* so = s + tid * OPITCH;
        #pragma unroll
        for (int j = 0; j < 24; ++j) {
            so[j * 3 + 0] = px[j];
            so[j * 3 + 1] = py[j];
            so[j * 3 + 2] = pz[j];
        }
    }
    __syncthreads();

    // ---- Drain: lane-stride-1 LDS, coalesced STG ----
    float* ob = out + (size_t)base * 72;
    const int ototal = nb * 72;            // 4608 for a full block
    #pragma unroll 8
    for (int i = tid; i < ototal; i += THREADS) {
        int body = i / 72;
        int e    = i - body * 72;
        ob[i]    = s[body * OPITCH + e];
    }
}

extern "C" void kernel_launch(void* const* d_in, const int* in_sizes, int n_in,
                              void* d_out, int out_size)
{
    const float* R   = (const float*)d_in[0];   // (B, 24, 3, 3) fp32
    const float* off = (const float*)d_in[1];   // (24, 3) fp32
    float* out       = (float*)d_out;           // (B, 24, 3) fp32

    const int B    = in_sizes[0] / 216;
    const int grid = (B + BPB - 1) / BPB;       // 2048 blocks @ B=131072
    const size_t smem = (size_t)BPB * SPITCH * sizeof(float);  // 55,552 B

    cudaFuncSetAttribute(smpl_skel_kernel,
                         cudaFuncAttributeMaxDynamicSharedMemorySize, (int)smem);
    smpl_skel_kernel<<<grid, THREADS, smem>>>(R, off, out, B);
}